// round 9
// baseline (speedup 1.0000x reference)
#include <cuda_runtime.h>
#include <cuda_fp16.h>
#include <cstdint>
#include <cstddef>

// Problem dims
#define NB 16384      // batch rows
#define KD 512        // D_in == H
#define NH 1536       // 3*H
#define KS 512        // plain fp16, no split
#define HH 512        // hidden

// GEMM tiling: 128x128 CTA, 256 thr, 8 warps 4m x 2n, 2 CTAs/SM,
// K-chunk 64, 3-stage cp.async pipeline (wait -> sync -> issue -> compute)
#define TILE_M 128
#define TILE_N 128
#define TILE_K 64                    // fp16 elems per K chunk (128 bytes/row)
#define NCHUNK (KS / TILE_K)         // 8
#define STAGES 3
#define ROW_STRIDE 144               // 128B data + 16B skew; conflict-free ldmatrix
#define A_STAGE_BYTES (TILE_M * ROW_STRIDE)      // 18432
#define STAGE_BYTES (2 * A_STAGE_BYTES)          // 36864 (A then B)
#define SMEM_BYTES (STAGES * STAGE_BYTES)        // 110592

#define TOTA4 (NB * KD / 4)          // 2097152
#define TOTW4 (NH * KD / 4)          // 196608

// ---------------- scratch (device globals; no allocations allowed) ----------
__device__ __align__(16) __half g_Ax[(size_t)NB * KS];
__device__ __align__(16) __half g_Ah[(size_t)NB * KS];
__device__ __align__(16) __half g_Wi[(size_t)NH * KS];
__device__ __align__(16) __half g_Wh[(size_t)NH * KS];
__device__ __align__(16) __half g_XT[(size_t)NB * NH];   // fp16 GEMM outputs
__device__ __align__(16) __half g_HT[(size_t)NB * NH];

// ---------------- PTX helpers ----------------
__device__ __forceinline__ uint32_t smem_u32(const void* p) {
    uint32_t a;
    asm("{ .reg .u64 t; cvta.to.shared.u64 t, %1; cvt.u32.u64 %0, t; }"
        : "=r"(a) : "l"(p));
    return a;
}

__device__ __forceinline__ void cp16(uint32_t dst, const void* src) {
    asm volatile("cp.async.cg.shared.global [%0], [%1], 16;"
                 :: "r"(dst), "l"(src) : "memory");
}

__device__ __forceinline__ void ldm4(uint32_t* v, uint32_t addr) {
    asm volatile("ldmatrix.sync.aligned.m8n8.x4.shared.b16 {%0,%1,%2,%3}, [%4];"
                 : "=r"(v[0]), "=r"(v[1]), "=r"(v[2]), "=r"(v[3]) : "r"(addr));
}

__device__ __forceinline__ void mma16816(float* d, const uint32_t* a, const uint32_t* b) {
    asm volatile(
        "mma.sync.aligned.m16n8k16.row.col.f32.f16.f16.f32 "
        "{%0,%1,%2,%3}, {%4,%5,%6,%7}, {%8,%9}, {%0,%1,%2,%3};"
        : "+f"(d[0]), "+f"(d[1]), "+f"(d[2]), "+f"(d[3])
        : "r"(a[0]), "r"(a[1]), "r"(a[2]), "r"(a[3]), "r"(b[0]), "r"(b[1]));
}

// ---------------- kernel 1: fused fp32 -> fp16 cast for all 4 tensors -------
__global__ void convert_all_kernel(const float* __restrict__ x,
                                   const float* __restrict__ hx,
                                   const float* __restrict__ Wi,
                                   const float* __restrict__ Wh) {
    int i = blockIdx.x * blockDim.x + threadIdx.x;
    const float* src;
    __half2* dst;
    int base;
    if (i < TOTA4)                  { src = x;  dst = (__half2*)g_Ax; base = i; }
    else if (i < 2 * TOTA4)         { src = hx; dst = (__half2*)g_Ah; base = i - TOTA4; }
    else if (i < 2 * TOTA4 + TOTW4) { src = Wi; dst = (__half2*)g_Wi; base = i - 2 * TOTA4; }
    else                            { src = Wh; dst = (__half2*)g_Wh; base = i - 2 * TOTA4 - TOTW4; }
    float4 v = reinterpret_cast<const float4*>(src)[base];
    dst[2 * base]     = __floats2half2_rn(v.x, v.y);
    dst[2 * base + 1] = __floats2half2_rn(v.z, v.w);
}

// ---------------- kernel 2: mma.sync fp16 GEMM ------------------------------
// D[m][n] = sum_k A[m][k] * W[n][k]   (M=16384, N=1536, K=512 fp16)
// CTA 128x128, K-chunk 64, 3-stage pipeline, 8 warps (4m x 2n),
// warp tile 32x64 = 2x8 m16n8k16 fragments. Output stored fp16.
__global__ void __launch_bounds__(256, 2) gemm_kernel() {
    extern __shared__ char smem[];
    const uint32_t sb = smem_u32(smem);
    const int tid  = threadIdx.x;
    const int lane = tid & 31;
    const int wid  = tid >> 5;
    const int m0 = blockIdx.y * TILE_M;
    const int n0 = blockIdx.x * TILE_N;
    const int g  = blockIdx.z;

    const __half* __restrict__ Ap = g ? g_Ah : g_Ax;
    const __half* __restrict__ Wp = g ? g_Wh : g_Wi;
    __half* __restrict__ Op = g ? g_HT : g_XT;

    // --- cp.async mapping: one 128B row per thread ---
    // threads 0..127  -> A rows m0+tid
    // threads 128..255 -> B rows n0+(tid-128)
    const char* gsrc = (tid < 128)
        ? (const char*)(Ap + (size_t)(m0 + tid) * KS)
        : (const char*)(Wp + (size_t)(n0 + tid - 128) * KS);
    const uint32_t sdst = (tid < 128)
        ? (uint32_t)(tid * ROW_STRIDE)
        : (uint32_t)(A_STAGE_BYTES + (tid - 128) * ROW_STRIDE);

    // --- ldmatrix per-lane offsets ---
    const int wm = wid & 3;                // warp m index (0..3) -> 32 rows
    const int wn = wid >> 2;               // warp n index (0..1) -> 64 cols
    const int grp = lane >> 3;
    const int r8  = lane & 7;
    uint32_t aoff[2], boff[4];
#pragma unroll
    for (int t = 0; t < 2; t++)
        aoff[t] = (uint32_t)((wm * 32 + t * 16 + (grp & 1) * 8 + r8) * ROW_STRIDE
                             + (grp >> 1) * 16);
#pragma unroll
    for (int p = 0; p < 4; p++)
        boff[p] = (uint32_t)(A_STAGE_BYTES
                             + (wn * 64 + p * 16 + (grp >> 1) * 8 + r8) * ROW_STRIDE
                             + (grp & 1) * 16);

    float acc[2][8][4];
#pragma unroll
    for (int t = 0; t < 2; t++)
#pragma unroll
        for (int n = 0; n < 8; n++)
#pragma unroll
            for (int e = 0; e < 4; e++) acc[t][n][e] = 0.f;

    // --- pipeline ---
#define ISSUE_STAGE(c, stg)                                                  \
    do {                                                                     \
        if ((c) < NCHUNK) {                                                  \
            uint32_t s_ = sb + (uint32_t)(stg) * STAGE_BYTES + sdst;         \
            const char* g_ = gsrc + (size_t)(c) * 128;                       \
            _Pragma("unroll")                                                \
            for (int j_ = 0; j_ < 8; j_++)                                   \
                cp16(s_ + j_ * 16, g_ + j_ * 16);                            \
        }                                                                    \
        asm volatile("cp.async.commit_group;" ::: "memory");                 \
    } while (0)

    ISSUE_STAGE(0, 0);
    ISSUE_STAGE(1, 1);

    int wr = 2;   // stage to write (chunk c+2)
    int rd = 0;   // stage to read  (chunk c)
    for (int c = 0; c < NCHUNK; ++c) {
        asm volatile("cp.async.wait_group 1;" ::: "memory");
        __syncthreads();
        // issue after the barrier: stage 'wr' was read at iteration c-1 and
        // the barrier above orders those reads before this write.
        ISSUE_STAGE(c + 2, wr);
        wr = (wr == STAGES - 1) ? 0 : wr + 1;

        uint32_t s_ = sb + (uint32_t)rd * STAGE_BYTES;
        rd = (rd == STAGES - 1) ? 0 : rd + 1;
#pragma unroll
        for (int ks = 0; ks < 4; ks++) {
            uint32_t Afr[2][4];
            uint32_t Bfr[8][2];
#pragma unroll
            for (int t = 0; t < 2; t++)
                ldm4(Afr[t], s_ + aoff[t] + ks * 32);
#pragma unroll
            for (int p = 0; p < 4; p++) {
                uint32_t v[4];
                ldm4(v, s_ + boff[p] + ks * 32);
                Bfr[2 * p][0]     = v[0];
                Bfr[2 * p][1]     = v[1];
                Bfr[2 * p + 1][0] = v[2];
                Bfr[2 * p + 1][1] = v[3];
            }
#pragma unroll
            for (int t = 0; t < 2; t++)
#pragma unroll
                for (int n = 0; n < 8; n++)
                    mma16816(acc[t][n], Afr[t], Bfr[n]);
        }
    }

    // --- epilogue: convert to fp16, STG.32 per fragment pair ---
    const int row_base = m0 + wm * 32 + (lane >> 2);
    const int col_base = n0 + wn * 64 + (lane & 3) * 2;
#pragma unroll
    for (int t = 0; t < 2; t++) {
#pragma unroll
        for (int n = 0; n < 8; n++) {
            int rr = row_base + t * 16;
            int cc = col_base + n * 8;
            __half2 v0 = __floats2half2_rn(acc[t][n][0], acc[t][n][1]);
            __half2 v1 = __floats2half2_rn(acc[t][n][2], acc[t][n][3]);
            *reinterpret_cast<__half2*>(Op + (size_t)rr * NH + cc)       = v0;
            *reinterpret_cast<__half2*>(Op + (size_t)(rr + 8) * NH + cc) = v1;
        }
    }
}

// ---------------- kernel 3: fused LN-GRU epilogue ---------------------------
// one 256-thread block per batch row; XT/HT read as fp16
__global__ void __launch_bounds__(256) epilogue_kernel(
    const float* __restrict__ hx,
    const float* __restrict__ b_i,
    const float* __restrict__ b_h,
    float* __restrict__ out)
{
    const int r = blockIdx.x;
    const int t = threadIdx.x;
    const __half* xrow = g_XT + (size_t)r * NH;
    const __half* hrow = g_HT + (size_t)r * NH;

    float xv[6], hv[6];
    float sAx = 0.f, qAx = 0.f, sAh = 0.f, qAh = 0.f;
    float sBx = 0.f, qBx = 0.f, sBh = 0.f, qBh = 0.f;
#pragma unroll
    for (int i = 0; i < 6; i++) {
        int j = t + 256 * i;
        float xt = __half2float(xrow[j]) + b_i[j];
        float ht = __half2float(hrow[j]) + b_h[j];
        xv[i] = xt; hv[i] = ht;
        if (i < 4) { sAx += xt; qAx += xt * xt; sAh += ht; qAh += ht * ht; }
        else       { sBx += xt; qBx += xt * xt; sBh += ht; qBh += ht * ht; }
    }

    // block-wide reduction of 8 partials
    float v[8] = {sAx, qAx, sAh, qAh, sBx, qBx, sBh, qBh};
#pragma unroll
    for (int k = 0; k < 8; k++)
#pragma unroll
        for (int off = 16; off; off >>= 1)
            v[k] += __shfl_xor_sync(0xffffffffu, v[k], off);

    __shared__ float red[8][8];
    __shared__ float stats[8];
    int lane = t & 31, w = t >> 5;
    if (lane == 0) {
#pragma unroll
        for (int k = 0; k < 8; k++) red[w][k] = v[k];
    }
    __syncthreads();
    if (t < 8) {
        float s = 0.f;
#pragma unroll
        for (int k = 0; k < 8; k++) s += red[k][t];
        stats[t] = s;
    }
    __syncthreads();

    const float invA = 1.f / 1024.f, invB = 1.f / 512.f;
    float mAx = stats[0] * invA, vAx = stats[1] * invA - mAx * mAx;
    float mAh = stats[2] * invA, vAh = stats[3] * invA - mAh * mAh;
    float mBx = stats[4] * invB, vBx = stats[5] * invB - mBx * mBx;
    float mBh = stats[6] * invB, vBh = stats[7] * invB - mBh * mBh;
    float rAx = rsqrtf(vAx + 1e-5f);
    float rAh = rsqrtf(vAh + 1e-5f);
    float rBx = rsqrtf(vBx + 1e-5f);
    float rBh = rsqrtf(vBh + 1e-5f);

    float g0 = (xv[0] - mAx) * rAx + (hv[0] - mAh) * rAh;   // r_t[t]
    float g1 = (xv[1] - mAx) * rAx + (hv[1] - mAh) * rAh;   // r_t[t+256]
    float g2 = (xv[2] - mAx) * rAx + (hv[2] - mAh) * rAh;   // z_t[t]
    float g3 = (xv[3] - mAx) * rAx + (hv[3] - mAh) * rAh;   // z_t[t+256]
    float rg0 = 1.f / (1.f + expf(-g0));
    float rg1 = 1.f / (1.f + expf(-g1));
    float zg0 = 1.f / (1.f + expf(-g2));
    float zg1 = 1.f / (1.f + expf(-g3));

    float n0v = tanhf((xv[4] - mBx) * rBx + rg0 * ((hv[4] - mBh) * rBh));
    float n1v = tanhf((xv[5] - mBx) * rBx + rg1 * ((hv[5] - mBh) * rBh));

    const float* hxr = hx + (size_t)r * HH;
    float* outr = out + (size_t)r * HH;
    outr[t]       = zg0 * hxr[t]       + (1.f - zg0) * n0v;
    outr[t + 256] = zg1 * hxr[t + 256] + (1.f - zg1) * n1v;
}

// ---------------- launcher ----------------
extern "C" void kernel_launch(void* const* d_in, const int* in_sizes, int n_in,
                              void* d_out, int out_size) {
    const float* x  = (const float*)d_in[0];
    const float* hx = (const float*)d_in[1];
    const float* Wi = (const float*)d_in[2];
    const float* bi = (const float*)d_in[3];
    const float* Wh = (const float*)d_in[4];
    const float* bh = (const float*)d_in[5];
    float* out = (float*)d_out;
    (void)in_sizes; (void)n_in; (void)out_size;

    int total = 2 * TOTA4 + 2 * TOTW4;
    convert_all_kernel<<<(total + 255) / 256, 256>>>(x, hx, Wi, Wh);

    static bool attr_set = false;
    if (!attr_set) {
        cudaFuncSetAttribute(gemm_kernel,
                             cudaFuncAttributeMaxDynamicSharedMemorySize, SMEM_BYTES);
        attr_set = true;
    }
    gemm_kernel<<<dim3(NH / TILE_N, NB / TILE_M, 2), 256, SMEM_BYTES>>>();

    epilogue_kernel<<<NB, 256>>>(hx, bi, bh, out);
}

// round 10
// speedup vs baseline: 1.2397x; 1.2397x over previous
#include <cuda_runtime.h>
#include <cuda_fp16.h>
#include <cstdint>
#include <cstddef>

// Problem dims
#define NB 16384      // batch rows
#define KD 512        // D_in == H
#define NH 1536       // 3*H
#define KS 512        // plain fp16, no split
#define HH 512        // hidden

// GEMM tiling (proven best: 128x128 CTA, 256 thr, 8 warps 4m x 2n, 2 CTAs/SM,
// K-chunk 32, 5-stage cp.async with issue hoisted above wait)
#define TILE_M 128
#define TILE_N 128
#define TILE_K 32                    // fp16 elems per K chunk (64 bytes/row)
#define NCHUNK (KS / TILE_K)         // 16
#define STAGES 5
#define ROW_STRIDE 80                // 64B data + 16B skew; conflict-free ldmatrix
#define A_STAGE_BYTES (TILE_M * ROW_STRIDE)      // 10240
#define STAGE_BYTES (2 * A_STAGE_BYTES)          // 20480 (A then B)
#define SMEM_BYTES (STAGES * STAGE_BYTES)        // 102400

#define TOTA4 (NB * KD / 4)          // 2097152
#define TOTW4 (NH * KD / 4)          // 196608

// ---------------- scratch (device globals; no allocations allowed) ----------
__device__ __align__(16) __half g_Ax[(size_t)NB * KS];
__device__ __align__(16) __half g_Ah[(size_t)NB * KS];
__device__ __align__(16) __half g_Wi[(size_t)NH * KS];
__device__ __align__(16) __half g_Wh[(size_t)NH * KS];
__device__ __align__(16) __half g_XT[(size_t)NB * NH];   // fp16 GEMM outputs
__device__ __align__(16) __half g_HT[(size_t)NB * NH];

// ---------------- PTX helpers ----------------
__device__ __forceinline__ uint32_t smem_u32(const void* p) {
    uint32_t a;
    asm("{ .reg .u64 t; cvta.to.shared.u64 t, %1; cvt.u32.u64 %0, t; }"
        : "=r"(a) : "l"(p));
    return a;
}

__device__ __forceinline__ void cp16(uint32_t dst, const void* src) {
    asm volatile("cp.async.cg.shared.global [%0], [%1], 16;"
                 :: "r"(dst), "l"(src) : "memory");
}

__device__ __forceinline__ void ldm4(uint32_t* v, uint32_t addr) {
    asm volatile("ldmatrix.sync.aligned.m8n8.x4.shared.b16 {%0,%1,%2,%3}, [%4];"
                 : "=r"(v[0]), "=r"(v[1]), "=r"(v[2]), "=r"(v[3]) : "r"(addr));
}

__device__ __forceinline__ void mma16816(float* d, const uint32_t* a, const uint32_t* b) {
    asm volatile(
        "mma.sync.aligned.m16n8k16.row.col.f32.f16.f16.f32 "
        "{%0,%1,%2,%3}, {%4,%5,%6,%7}, {%8,%9}, {%0,%1,%2,%3};"
        : "+f"(d[0]), "+f"(d[1]), "+f"(d[2]), "+f"(d[3])
        : "r"(a[0]), "r"(a[1]), "r"(a[2]), "r"(a[3]), "r"(b[0]), "r"(b[1]));
}

// ---------------- kernel 1: fused fp32 -> fp16 cast for all 4 tensors -------
__global__ void convert_all_kernel(const float* __restrict__ x,
                                   const float* __restrict__ hx,
                                   const float* __restrict__ Wi,
                                   const float* __restrict__ Wh) {
    int i = blockIdx.x * blockDim.x + threadIdx.x;
    const float* src;
    __half2* dst;
    int base;
    if (i < TOTA4)                  { src = x;  dst = (__half2*)g_Ax; base = i; }
    else if (i < 2 * TOTA4)         { src = hx; dst = (__half2*)g_Ah; base = i - TOTA4; }
    else if (i < 2 * TOTA4 + TOTW4) { src = Wi; dst = (__half2*)g_Wi; base = i - 2 * TOTA4; }
    else                            { src = Wh; dst = (__half2*)g_Wh; base = i - 2 * TOTA4 - TOTW4; }
    float4 v = reinterpret_cast<const float4*>(src)[base];
    dst[2 * base]     = __floats2half2_rn(v.x, v.y);
    dst[2 * base + 1] = __floats2half2_rn(v.z, v.w);
}

// ---------------- kernel 2: mma.sync fp16 GEMM ------------------------------
// D[m][n] = sum_k A[m][k] * W[n][k]   (M=16384, N=1536, K=512 fp16)
// CTA 128x128, K-chunk 32, 5-stage pipeline, 8 warps (4m x 2n),
// warp tile 32x64 = 2x8 m16n8k16 fragments. Output stored fp16.
__global__ void __launch_bounds__(256, 2) gemm_kernel() {
    extern __shared__ char smem[];
    const uint32_t sb = smem_u32(smem);
    const int tid  = threadIdx.x;
    const int lane = tid & 31;
    const int wid  = tid >> 5;
    const int m0 = blockIdx.y * TILE_M;
    const int n0 = blockIdx.x * TILE_N;
    const int g  = blockIdx.z;

    const __half* __restrict__ Ap = g ? g_Ah : g_Ax;
    const __half* __restrict__ Wp = g ? g_Wh : g_Wi;
    __half* __restrict__ Op = g ? g_HT : g_XT;

    // --- cp.async mapping: 512 16B chunks per matrix, 2 per thread ---
    const char* asrc[2];
    const char* bsrc[2];
    uint32_t    adst[2], bdst[2];
#pragma unroll
    for (int j = 0; j < 2; j++) {
        int q   = tid * 2 + j;
        int row = q >> 2;
        int cb  = (q & 3) * 16;            // byte offset within 64B row
        asrc[j] = (const char*)(Ap + (size_t)(m0 + row) * KS) + cb;
        bsrc[j] = (const char*)(Wp + (size_t)(n0 + row) * KS) + cb;
        adst[j] = (uint32_t)(row * ROW_STRIDE + cb);
        bdst[j] = (uint32_t)(A_STAGE_BYTES + row * ROW_STRIDE + cb);
    }

    // --- ldmatrix per-lane offsets ---
    const int wm = wid & 3;                // warp m index (0..3) -> 32 rows
    const int wn = wid >> 2;               // warp n index (0..1) -> 64 cols
    const int grp = lane >> 3;
    const int r8  = lane & 7;
    uint32_t aoff[2], boff[4];
#pragma unroll
    for (int t = 0; t < 2; t++)
        aoff[t] = (uint32_t)((wm * 32 + t * 16 + (grp & 1) * 8 + r8) * ROW_STRIDE
                             + (grp >> 1) * 16);
#pragma unroll
    for (int p = 0; p < 4; p++)
        boff[p] = (uint32_t)(A_STAGE_BYTES
                             + (wn * 64 + p * 16 + (grp >> 1) * 8 + r8) * ROW_STRIDE
                             + (grp & 1) * 16);

    float acc[2][8][4];
#pragma unroll
    for (int t = 0; t < 2; t++)
#pragma unroll
        for (int n = 0; n < 8; n++)
#pragma unroll
            for (int e = 0; e < 4; e++) acc[t][n][e] = 0.f;

    // --- pipeline ---
#define ISSUE_STAGE(c, stg)                                                  \
    do {                                                                     \
        if ((c) < NCHUNK) {                                                  \
            uint32_t s_ = sb + (uint32_t)(stg) * STAGE_BYTES;                \
            _Pragma("unroll")                                                \
            for (int j_ = 0; j_ < 2; j_++) {                                 \
                cp16(s_ + adst[j_], asrc[j_] + (size_t)(c) * 64);            \
                cp16(s_ + bdst[j_], bsrc[j_] + (size_t)(c) * 64);            \
            }                                                                \
        }                                                                    \
        asm volatile("cp.async.commit_group;" ::: "memory");                 \
    } while (0)

    ISSUE_STAGE(0, 0);
    ISSUE_STAGE(1, 1);
    ISSUE_STAGE(2, 2);

    int wr = 3;   // stage to write (chunk c+3)
    int rd = 0;   // stage to read  (chunk c)
    for (int c = 0; c < NCHUNK; ++c) {
        // Issue ahead-of-wait: buffer 'wr' was last read at iteration c-2 and
        // a barrier at c-1 separates those reads from this write.
        ISSUE_STAGE(c + 3, wr);
        wr = (wr == STAGES - 1) ? 0 : wr + 1;
        asm volatile("cp.async.wait_group 3;" ::: "memory");
        __syncthreads();

        uint32_t s_ = sb + (uint32_t)rd * STAGE_BYTES;
        rd = (rd == STAGES - 1) ? 0 : rd + 1;
#pragma unroll
        for (int ks = 0; ks < 2; ks++) {
            uint32_t Afr[2][4];
            uint32_t Bfr[8][2];
#pragma unroll
            for (int t = 0; t < 2; t++)
                ldm4(Afr[t], s_ + aoff[t] + ks * 32);
#pragma unroll
            for (int p = 0; p < 4; p++) {
                uint32_t v[4];
                ldm4(v, s_ + boff[p] + ks * 32);
                Bfr[2 * p][0]     = v[0];
                Bfr[2 * p][1]     = v[1];
                Bfr[2 * p + 1][0] = v[2];
                Bfr[2 * p + 1][1] = v[3];
            }
#pragma unroll
            for (int t = 0; t < 2; t++)
#pragma unroll
                for (int n = 0; n < 8; n++)
                    mma16816(acc[t][n], Afr[t], Bfr[n]);
        }
    }

    // --- epilogue: convert to fp16, STG.32 per fragment pair ---
    const int row_base = m0 + wm * 32 + (lane >> 2);
    const int col_base = n0 + wn * 64 + (lane & 3) * 2;
#pragma unroll
    for (int t = 0; t < 2; t++) {
#pragma unroll
        for (int n = 0; n < 8; n++) {
            int rr = row_base + t * 16;
            int cc = col_base + n * 8;
            __half2 v0 = __floats2half2_rn(acc[t][n][0], acc[t][n][1]);
            __half2 v1 = __floats2half2_rn(acc[t][n][2], acc[t][n][3]);
            *reinterpret_cast<__half2*>(Op + (size_t)rr * NH + cc)       = v0;
            *reinterpret_cast<__half2*>(Op + (size_t)(rr + 8) * NH + cc) = v1;
        }
    }
}

// ---------------- kernel 3: fused LN-GRU epilogue (vectorized) --------------
// one 256-thread block per batch row; thread t owns output columns 2t, 2t+1.
// Column-pair layout within a 1536-wide row:
//   pair i=0 -> cols (2t, 2t+1)           in [0,512)    = r-gate slots
//   pair i=1 -> cols 512 + (2t, 2t+1)     in [512,1024) = z-gate slots
//   pair i=2 -> cols 1024 + (2t, 2t+1)    in [1024,1536)= candidate slots
__global__ void __launch_bounds__(256) epilogue_kernel(
    const float* __restrict__ hx,
    const float* __restrict__ b_i,
    const float* __restrict__ b_h,
    float* __restrict__ out)
{
    const int r = blockIdx.x;
    const int t = threadIdx.x;
    const __half2* xrow = reinterpret_cast<const __half2*>(g_XT + (size_t)r * NH);
    const __half2* hrow = reinterpret_cast<const __half2*>(g_HT + (size_t)r * NH);

    float2 xv[3], hv[3];
    float sAx = 0.f, qAx = 0.f, sAh = 0.f, qAh = 0.f;
    float sBx = 0.f, qBx = 0.f, sBh = 0.f, qBh = 0.f;
#pragma unroll
    for (int i = 0; i < 3; i++) {
        int idx = t + 256 * i;                  // half2 index; col = 2*idx
        float2 xf = __half22float2(xrow[idx]);
        float2 hf = __half22float2(hrow[idx]);
        float2 bi2 = *reinterpret_cast<const float2*>(b_i + 2 * idx);
        float2 bh2 = *reinterpret_cast<const float2*>(b_h + 2 * idx);
        xf.x += bi2.x; xf.y += bi2.y;
        hf.x += bh2.x; hf.y += bh2.y;
        xv[i] = xf; hv[i] = hf;
        if (i < 2) {
            sAx += xf.x + xf.y; qAx += xf.x * xf.x + xf.y * xf.y;
            sAh += hf.x + hf.y; qAh += hf.x * hf.x + hf.y * hf.y;
        } else {
            sBx += xf.x + xf.y; qBx += xf.x * xf.x + xf.y * xf.y;
            sBh += hf.x + hf.y; qBh += hf.x * hf.x + hf.y * hf.y;
        }
    }

    // block-wide reduction of 8 partials
    float v[8] = {sAx, qAx, sAh, qAh, sBx, qBx, sBh, qBh};
#pragma unroll
    for (int k = 0; k < 8; k++)
#pragma unroll
        for (int off = 16; off; off >>= 1)
            v[k] += __shfl_xor_sync(0xffffffffu, v[k], off);

    __shared__ float red[8][8];
    __shared__ float stats[8];
    int lane = t & 31, w = t >> 5;
    if (lane == 0) {
#pragma unroll
        for (int k = 0; k < 8; k++) red[w][k] = v[k];
    }
    __syncthreads();
    if (t < 8) {
        float s = 0.f;
#pragma unroll
        for (int k = 0; k < 8; k++) s += red[k][t];
        stats[t] = s;
    }
    __syncthreads();

    const float invA = 1.f / 1024.f, invB = 1.f / 512.f;
    float mAx = stats[0] * invA, vAx = stats[1] * invA - mAx * mAx;
    float mAh = stats[2] * invA, vAh = stats[3] * invA - mAh * mAh;
    float mBx = stats[4] * invB, vBx = stats[5] * invB - mBx * mBx;
    float mBh = stats[6] * invB, vBh = stats[7] * invB - mBh * mBh;
    float rAx = rsqrtf(vAx + 1e-5f);
    float rAh = rsqrtf(vAh + 1e-5f);
    float rBx = rsqrtf(vBx + 1e-5f);
    float rBh = rsqrtf(vBh + 1e-5f);

    // gates, componentwise over the column pair (2t, 2t+1)
    float gr0 = (xv[0].x - mAx) * rAx + (hv[0].x - mAh) * rAh;
    float gr1 = (xv[0].y - mAx) * rAx + (hv[0].y - mAh) * rAh;
    float gz0 = (xv[1].x - mAx) * rAx + (hv[1].x - mAh) * rAh;
    float gz1 = (xv[1].y - mAx) * rAx + (hv[1].y - mAh) * rAh;
    float rg0 = 1.f / (1.f + expf(-gr0));
    float rg1 = 1.f / (1.f + expf(-gr1));
    float zg0 = 1.f / (1.f + expf(-gz0));
    float zg1 = 1.f / (1.f + expf(-gz1));

    float n0v = tanhf((xv[2].x - mBx) * rBx + rg0 * ((hv[2].x - mBh) * rBh));
    float n1v = tanhf((xv[2].y - mBx) * rBx + rg1 * ((hv[2].y - mBh) * rBh));

    float2 hx2 = *reinterpret_cast<const float2*>(hx + (size_t)r * HH + 2 * t);
    float2 o;
    o.x = zg0 * hx2.x + (1.f - zg0) * n0v;
    o.y = zg1 * hx2.y + (1.f - zg1) * n1v;
    *reinterpret_cast<float2*>(out + (size_t)r * HH + 2 * t) = o;
}

// ---------------- launcher ----------------
extern "C" void kernel_launch(void* const* d_in, const int* in_sizes, int n_in,
                              void* d_out, int out_size) {
    const float* x  = (const float*)d_in[0];
    const float* hx = (const float*)d_in[1];
    const float* Wi = (const float*)d_in[2];
    const float* bi = (const float*)d_in[3];
    const float* Wh = (const float*)d_in[4];
    const float* bh = (const float*)d_in[5];
    float* out = (float*)d_out;
    (void)in_sizes; (void)n_in; (void)out_size;

    int total = 2 * TOTA4 + 2 * TOTW4;
    convert_all_kernel<<<(total + 255) / 256, 256>>>(x, hx, Wi, Wh);

    static bool attr_set = false;
    if (!attr_set) {
        cudaFuncSetAttribute(gemm_kernel,
                             cudaFuncAttributeMaxDynamicSharedMemorySize, SMEM_BYTES);
        attr_set = true;
    }
    gemm_kernel<<<dim3(NH / TILE_N, NB / TILE_M, 2), 256, SMEM_BYTES>>>();

    epilogue_kernel<<<NB, 256>>>(hx, bi, bh, out);
}

// round 12
// speedup vs baseline: 1.2493x; 1.0077x over previous
#include <cuda_runtime.h>
#include <cuda_fp16.h>
#include <cstdint>
#include <cstddef>

// Problem dims
#define NB 16384      // batch rows
#define KD 512        // D_in == H
#define NH 1536       // 3*H
#define KS 512        // plain fp16, no split
#define HH 512        // hidden

// GEMM tiling (proven best: 128x128 CTA, 256 thr, 8 warps 4m x 2n, 2 CTAs/SM,
// K-chunk 32, 5-stage cp.async with issue hoisted above wait)
#define TILE_M 128
#define TILE_N 128
#define TILE_K 32                    // fp16 elems per K chunk (64 bytes/row)
#define NCHUNK (KS / TILE_K)         // 16
#define STAGES 5
#define ROW_STRIDE 80                // 64B data + 16B skew; conflict-free ldmatrix
#define A_STAGE_BYTES (TILE_M * ROW_STRIDE)      // 10240
#define STAGE_BYTES (2 * A_STAGE_BYTES)          // 20480 (A then B)
#define SMEM_BYTES (STAGES * STAGE_BYTES)        // 102400

#define TOT8A (NB * KD / 8)          // 1048576 8-float chunks in x (and hx)
#define TOT8W (NH * KD / 8)          // 98304 in each W

// ---------------- scratch (device globals; no allocations allowed) ----------
__device__ __align__(16) __half g_Ax[(size_t)NB * KS];
__device__ __align__(16) __half g_Ah[(size_t)NB * KS];
__device__ __align__(16) __half g_Wi[(size_t)NH * KS];
__device__ __align__(16) __half g_Wh[(size_t)NH * KS];
__device__ __align__(16) __half g_XT[(size_t)NB * NH];   // fp16 GEMM outputs
__device__ __align__(16) __half g_HT[(size_t)NB * NH];

// ---------------- PTX helpers ----------------
__device__ __forceinline__ uint32_t smem_u32(const void* p) {
    uint32_t a;
    asm("{ .reg .u64 t; cvta.to.shared.u64 t, %1; cvt.u32.u64 %0, t; }"
        : "=r"(a) : "l"(p));
    return a;
}

__device__ __forceinline__ void cp16(uint32_t dst, const void* src) {
    asm volatile("cp.async.cg.shared.global [%0], [%1], 16;"
                 :: "r"(dst), "l"(src) : "memory");
}

__device__ __forceinline__ void ldm4(uint32_t* v, uint32_t addr) {
    asm volatile("ldmatrix.sync.aligned.m8n8.x4.shared.b16 {%0,%1,%2,%3}, [%4];"
                 : "=r"(v[0]), "=r"(v[1]), "=r"(v[2]), "=r"(v[3]) : "r"(addr));
}

__device__ __forceinline__ void mma16816(float* d, const uint32_t* a, const uint32_t* b) {
    asm volatile(
        "mma.sync.aligned.m16n8k16.row.col.f32.f16.f16.f32 "
        "{%0,%1,%2,%3}, {%4,%5,%6,%7}, {%8,%9}, {%0,%1,%2,%3};"
        : "+f"(d[0]), "+f"(d[1]), "+f"(d[2]), "+f"(d[3])
        : "r"(a[0]), "r"(a[1]), "r"(a[2]), "r"(a[3]), "r"(b[0]), "r"(b[1]));
}

__device__ __forceinline__ uint32_t h2_bits(__half2 h) {
    uint32_t u;
    u = *reinterpret_cast<uint32_t*>(&h);
    return u;
}

// ---------------- kernel 1: fused fp32 -> fp16 cast, 8 floats/thread --------
__global__ void convert_all_kernel(const float* __restrict__ x,
                                   const float* __restrict__ hx,
                                   const float* __restrict__ Wi,
                                   const float* __restrict__ Wh) {
    int i = blockIdx.x * blockDim.x + threadIdx.x;
    const float* src;
    uint4* dst;
    int base;
    if (i < TOT8A)                  { src = x;  dst = (uint4*)g_Ax; base = i; }
    else if (i < 2 * TOT8A)         { src = hx; dst = (uint4*)g_Ah; base = i - TOT8A; }
    else if (i < 2 * TOT8A + TOT8W) { src = Wi; dst = (uint4*)g_Wi; base = i - 2 * TOT8A; }
    else                            { src = Wh; dst = (uint4*)g_Wh; base = i - 2 * TOT8A - TOT8W; }
    float4 v0 = reinterpret_cast<const float4*>(src)[2 * base];
    float4 v1 = reinterpret_cast<const float4*>(src)[2 * base + 1];
    uint4 o;
    o.x = h2_bits(__floats2half2_rn(v0.x, v0.y));
    o.y = h2_bits(__floats2half2_rn(v0.z, v0.w));
    o.z = h2_bits(__floats2half2_rn(v1.x, v1.y));
    o.w = h2_bits(__floats2half2_rn(v1.z, v1.w));
    dst[base] = o;
}

// ---------------- kernel 2: mma.sync fp16 GEMM (FROZEN R10 winner) ----------
// D[m][n] = sum_k A[m][k] * W[n][k]   (M=16384, N=1536, K=512 fp16)
// CTA 128x128, K-chunk 32, 5-stage pipeline, 8 warps (4m x 2n),
// warp tile 32x64 = 2x8 m16n8k16 fragments. Output stored fp16.
__global__ void __launch_bounds__(256, 2) gemm_kernel() {
    extern __shared__ char smem[];
    const uint32_t sb = smem_u32(smem);
    const int tid  = threadIdx.x;
    const int lane = tid & 31;
    const int wid  = tid >> 5;
    const int m0 = blockIdx.y * TILE_M;
    const int n0 = blockIdx.x * TILE_N;
    const int g  = blockIdx.z;

    const __half* __restrict__ Ap = g ? g_Ah : g_Ax;
    const __half* __restrict__ Wp = g ? g_Wh : g_Wi;
    __half* __restrict__ Op = g ? g_HT : g_XT;

    // --- cp.async mapping: 512 16B chunks per matrix, 2 per thread ---
    const char* asrc[2];
    const char* bsrc[2];
    uint32_t    adst[2], bdst[2];
#pragma unroll
    for (int j = 0; j < 2; j++) {
        int q   = tid * 2 + j;
        int row = q >> 2;
        int cb  = (q & 3) * 16;            // byte offset within 64B row
        asrc[j] = (const char*)(Ap + (size_t)(m0 + row) * KS) + cb;
        bsrc[j] = (const char*)(Wp + (size_t)(n0 + row) * KS) + cb;
        adst[j] = (uint32_t)(row * ROW_STRIDE + cb);
        bdst[j] = (uint32_t)(A_STAGE_BYTES + row * ROW_STRIDE + cb);
    }

    // --- ldmatrix per-lane offsets ---
    const int wm = wid & 3;                // warp m index (0..3) -> 32 rows
    const int wn = wid >> 2;               // warp n index (0..1) -> 64 cols
    const int grp = lane >> 3;
    const int r8  = lane & 7;
    uint32_t aoff[2], boff[4];
#pragma unroll
    for (int t = 0; t < 2; t++)
        aoff[t] = (uint32_t)((wm * 32 + t * 16 + (grp & 1) * 8 + r8) * ROW_STRIDE
                             + (grp >> 1) * 16);
#pragma unroll
    for (int p = 0; p < 4; p++)
        boff[p] = (uint32_t)(A_STAGE_BYTES
                             + (wn * 64 + p * 16 + (grp >> 1) * 8 + r8) * ROW_STRIDE
                             + (grp & 1) * 16);

    float acc[2][8][4];
#pragma unroll
    for (int t = 0; t < 2; t++)
#pragma unroll
        for (int n = 0; n < 8; n++)
#pragma unroll
            for (int e = 0; e < 4; e++) acc[t][n][e] = 0.f;

    // --- pipeline ---
#define ISSUE_STAGE(c, stg)                                                  \
    do {                                                                     \
        if ((c) < NCHUNK) {                                                  \
            uint32_t s_ = sb + (uint32_t)(stg) * STAGE_BYTES;                \
            _Pragma("unroll")                                                \
            for (int j_ = 0; j_ < 2; j_++) {                                 \
                cp16(s_ + adst[j_], asrc[j_] + (size_t)(c) * 64);            \
                cp16(s_ + bdst[j_], bsrc[j_] + (size_t)(c) * 64);            \
            }                                                                \
        }                                                                    \
        asm volatile("cp.async.commit_group;" ::: "memory");                 \
    } while (0)

    ISSUE_STAGE(0, 0);
    ISSUE_STAGE(1, 1);
    ISSUE_STAGE(2, 2);

    int wr = 3;   // stage to write (chunk c+3)
    int rd = 0;   // stage to read  (chunk c)
    for (int c = 0; c < NCHUNK; ++c) {
        // Issue ahead-of-wait: buffer 'wr' was last read at iteration c-2 and
        // a barrier at c-1 separates those reads from this write.
        ISSUE_STAGE(c + 3, wr);
        wr = (wr == STAGES - 1) ? 0 : wr + 1;
        asm volatile("cp.async.wait_group 3;" ::: "memory");
        __syncthreads();

        uint32_t s_ = sb + (uint32_t)rd * STAGE_BYTES;
        rd = (rd == STAGES - 1) ? 0 : rd + 1;
#pragma unroll
        for (int ks = 0; ks < 2; ks++) {
            uint32_t Afr[2][4];
            uint32_t Bfr[8][2];
#pragma unroll
            for (int t = 0; t < 2; t++)
                ldm4(Afr[t], s_ + aoff[t] + ks * 32);
#pragma unroll
            for (int p = 0; p < 4; p++) {
                uint32_t v[4];
                ldm4(v, s_ + boff[p] + ks * 32);
                Bfr[2 * p][0]     = v[0];
                Bfr[2 * p][1]     = v[1];
                Bfr[2 * p + 1][0] = v[2];
                Bfr[2 * p + 1][1] = v[3];
            }
#pragma unroll
            for (int t = 0; t < 2; t++)
#pragma unroll
                for (int n = 0; n < 8; n++)
                    mma16816(acc[t][n], Afr[t], Bfr[n]);
        }
    }

    // --- epilogue: convert to fp16, STG.32 per fragment pair ---
    const int row_base = m0 + wm * 32 + (lane >> 2);
    const int col_base = n0 + wn * 64 + (lane & 3) * 2;
#pragma unroll
    for (int t = 0; t < 2; t++) {
#pragma unroll
        for (int n = 0; n < 8; n++) {
            int rr = row_base + t * 16;
            int cc = col_base + n * 8;
            __half2 v0 = __floats2half2_rn(acc[t][n][0], acc[t][n][1]);
            __half2 v1 = __floats2half2_rn(acc[t][n][2], acc[t][n][3]);
            *reinterpret_cast<__half2*>(Op + (size_t)rr * NH + cc)       = v0;
            *reinterpret_cast<__half2*>(Op + (size_t)(rr + 8) * NH + cc) = v1;
        }
    }
}

// ---------------- kernel 3: fused LN-GRU epilogue (vectorized) --------------
// one 256-thread block per batch row; thread t owns output columns 2t, 2t+1.
__global__ void __launch_bounds__(256) epilogue_kernel(
    const float* __restrict__ hx,
    const float* __restrict__ b_i,
    const float* __restrict__ b_h,
    float* __restrict__ out)
{
    const int r = blockIdx.x;
    const int t = threadIdx.x;
    const __half2* xrow = reinterpret_cast<const __half2*>(g_XT + (size_t)r * NH);
    const __half2* hrow = reinterpret_cast<const __half2*>(g_HT + (size_t)r * NH);

    float2 xv[3], hv[3];
    float sAx = 0.f, qAx = 0.f, sAh = 0.f, qAh = 0.f;
    float sBx = 0.f, qBx = 0.f, sBh = 0.f, qBh = 0.f;
#pragma unroll
    for (int i = 0; i < 3; i++) {
        int idx = t + 256 * i;                  // half2 index; col = 2*idx
        float2 xf = __half22float2(xrow[idx]);
        float2 hf = __half22float2(hrow[idx]);
        float2 bi2 = *reinterpret_cast<const float2*>(b_i + 2 * idx);
        float2 bh2 = *reinterpret_cast<const float2*>(b_h + 2 * idx);
        xf.x += bi2.x; xf.y += bi2.y;
        hf.x += bh2.x; hf.y += bh2.y;
        xv[i] = xf; hv[i] = hf;
        if (i < 2) {
            sAx += xf.x + xf.y; qAx += xf.x * xf.x + xf.y * xf.y;
            sAh += hf.x + hf.y; qAh += hf.x * hf.x + hf.y * hf.y;
        } else {
            sBx += xf.x + xf.y; qBx += xf.x * xf.x + xf.y * xf.y;
            sBh += hf.x + hf.y; qBh += hf.x * hf.x + hf.y * hf.y;
        }
    }

    // block-wide reduction of 8 partials
    float v[8] = {sAx, qAx, sAh, qAh, sBx, qBx, sBh, qBh};
#pragma unroll
    for (int k = 0; k < 8; k++)
#pragma unroll
        for (int off = 16; off; off >>= 1)
            v[k] += __shfl_xor_sync(0xffffffffu, v[k], off);

    __shared__ float red[8][8];
    __shared__ float stats[8];
    int lane = t & 31, w = t >> 5;
    if (lane == 0) {
#pragma unroll
        for (int k = 0; k < 8; k++) red[w][k] = v[k];
    }
    __syncthreads();
    if (t < 8) {
        float s = 0.f;
#pragma unroll
        for (int k = 0; k < 8; k++) s += red[k][t];
        stats[t] = s;
    }
    __syncthreads();

    const float invA = 1.f / 1024.f, invB = 1.f / 512.f;
    float mAx = stats[0] * invA, vAx = stats[1] * invA - mAx * mAx;
    float mAh = stats[2] * invA, vAh = stats[3] * invA - mAh * mAh;
    float mBx = stats[4] * invB, vBx = stats[5] * invB - mBx * mBx;
    float mBh = stats[6] * invB, vBh = stats[7] * invB - mBh * mBh;
    float rAx = rsqrtf(vAx + 1e-5f);
    float rAh = rsqrtf(vAh + 1e-5f);
    float rBx = rsqrtf(vBx + 1e-5f);
    float rBh = rsqrtf(vBh + 1e-5f);

    float gr0 = (xv[0].x - mAx) * rAx + (hv[0].x - mAh) * rAh;
    float gr1 = (xv[0].y - mAx) * rAx + (hv[0].y - mAh) * rAh;
    float gz0 = (xv[1].x - mAx) * rAx + (hv[1].x - mAh) * rAh;
    float gz1 = (xv[1].y - mAx) * rAx + (hv[1].y - mAh) * rAh;
    float rg0 = 1.f / (1.f + expf(-gr0));
    float rg1 = 1.f / (1.f + expf(-gr1));
    float zg0 = 1.f / (1.f + expf(-gz0));
    float zg1 = 1.f / (1.f + expf(-gz1));

    float n0v = tanhf((xv[2].x - mBx) * rBx + rg0 * ((hv[2].x - mBh) * rBh));
    float n1v = tanhf((xv[2].y - mBx) * rBx + rg1 * ((hv[2].y - mBh) * rBh));

    float2 hx2 = *reinterpret_cast<const float2*>(hx + (size_t)r * HH + 2 * t);
    float2 o;
    o.x = zg0 * hx2.x + (1.f - zg0) * n0v;
    o.y = zg1 * hx2.y + (1.f - zg1) * n1v;
    *reinterpret_cast<float2*>(out + (size_t)r * HH + 2 * t) = o;
}

// ---------------- launcher ----------------
extern "C" void kernel_launch(void* const* d_in, const int* in_sizes, int n_in,
                              void* d_out, int out_size) {
    const float* x  = (const float*)d_in[0];
    const float* hx = (const float*)d_in[1];
    const float* Wi = (const float*)d_in[2];
    const float* bi = (const float*)d_in[3];
    const float* Wh = (const float*)d_in[4];
    const float* bh = (const float*)d_in[5];
    float* out = (float*)d_out;
    (void)in_sizes; (void)n_in; (void)out_size;

    int total = 2 * TOT8A + 2 * TOT8W;
    convert_all_kernel<<<(total + 255) / 256, 256>>>(x, hx, Wi, Wh);

    static bool attr_set = false;
    if (!attr_set) {
        cudaFuncSetAttribute(gemm_kernel,
                             cudaFuncAttributeMaxDynamicSharedMemorySize, SMEM_BYTES);
        attr_set = true;
    }
    gemm_kernel<<<dim3(NH / TILE_N, NB / TILE_M, 2), 256, SMEM_BYTES>>>();

    epilogue_kernel<<<NB, 256>>>(hx, bi, bh, out);
}

// round 14
// speedup vs baseline: 1.2863x; 1.0297x over previous
#include <cuda_runtime.h>
#include <cuda_fp16.h>
#include <cstdint>
#include <cstddef>

// Problem dims
#define NB 16384      // batch rows
#define KD 512        // D_in == H
#define NH 1536       // 3*H
#define KS 512        // plain fp16, no split
#define HH 512        // hidden

// GEMM tiling (proven best: 128x128 CTA, 256 thr, 8 warps 4m x 2n, 2 CTAs/SM,
// K-chunk 32, 5-stage cp.async with issue hoisted above wait)
#define TILE_M 128
#define TILE_N 128
#define TILE_K 32                    // fp16 elems per K chunk (64 bytes/row)
#define NCHUNK (KS / TILE_K)         // 16
#define STAGES 5
#define ROW_STRIDE 80                // 64B data + 16B skew; conflict-free ldmatrix
#define A_STAGE_BYTES (TILE_M * ROW_STRIDE)      // 10240
#define STAGE_BYTES (2 * A_STAGE_BYTES)          // 20480 (A then B)
#define SMEM_BYTES (STAGES * STAGE_BYTES)        // 102400

#define TOT8A (NB * KD / 8)          // 1048576 8-float chunks in x (and hx)
#define TOT8W (NH * KD / 8)          // 98304 in each W

// ---------------- scratch (device globals; no allocations allowed) ----------
__device__ __align__(16) __half g_Ax[(size_t)NB * KS];
__device__ __align__(16) __half g_Ah[(size_t)NB * KS];
__device__ __align__(16) __half g_Wi[(size_t)NH * KS];
__device__ __align__(16) __half g_Wh[(size_t)NH * KS];
__device__ __align__(16) __half g_XT[(size_t)NB * NH];   // fp16 GEMM outputs
__device__ __align__(16) __half g_HT[(size_t)NB * NH];

// ---------------- PTX helpers ----------------
__device__ __forceinline__ uint32_t smem_u32(const void* p) {
    uint32_t a;
    asm("{ .reg .u64 t; cvta.to.shared.u64 t, %1; cvt.u32.u64 %0, t; }"
        : "=r"(a) : "l"(p));
    return a;
}

__device__ __forceinline__ void cp16(uint32_t dst, const void* src) {
    asm volatile("cp.async.cg.shared.global [%0], [%1], 16;"
                 :: "r"(dst), "l"(src) : "memory");
}

__device__ __forceinline__ void ldm4(uint32_t* v, uint32_t addr) {
    asm volatile("ldmatrix.sync.aligned.m8n8.x4.shared.b16 {%0,%1,%2,%3}, [%4];"
                 : "=r"(v[0]), "=r"(v[1]), "=r"(v[2]), "=r"(v[3]) : "r"(addr));
}

__device__ __forceinline__ void mma16816(float* d, const uint32_t* a, const uint32_t* b) {
    asm volatile(
        "mma.sync.aligned.m16n8k16.row.col.f32.f16.f16.f32 "
        "{%0,%1,%2,%3}, {%4,%5,%6,%7}, {%8,%9}, {%0,%1,%2,%3};"
        : "+f"(d[0]), "+f"(d[1]), "+f"(d[2]), "+f"(d[3])
        : "r"(a[0]), "r"(a[1]), "r"(a[2]), "r"(a[3]), "r"(b[0]), "r"(b[1]));
}

__device__ __forceinline__ uint32_t h2_bits(__half2 h) {
    return *reinterpret_cast<uint32_t*>(&h);
}

// ---------------- kernel 1: fused fp32 -> fp16 cast, 8 floats/thread --------
__global__ void convert_all_kernel(const float* __restrict__ x,
                                   const float* __restrict__ hx,
                                   const float* __restrict__ Wi,
                                   const float* __restrict__ Wh) {
    int i = blockIdx.x * blockDim.x + threadIdx.x;
    const float* src;
    uint4* dst;
    int base;
    if (i < TOT8A)                  { src = x;  dst = (uint4*)g_Ax; base = i; }
    else if (i < 2 * TOT8A)         { src = hx; dst = (uint4*)g_Ah; base = i - TOT8A; }
    else if (i < 2 * TOT8A + TOT8W) { src = Wi; dst = (uint4*)g_Wi; base = i - 2 * TOT8A; }
    else                            { src = Wh; dst = (uint4*)g_Wh; base = i - 2 * TOT8A - TOT8W; }
    float4 v0 = reinterpret_cast<const float4*>(src)[2 * base];
    float4 v1 = reinterpret_cast<const float4*>(src)[2 * base + 1];
    uint4 o;
    o.x = h2_bits(__floats2half2_rn(v0.x, v0.y));
    o.y = h2_bits(__floats2half2_rn(v0.z, v0.w));
    o.z = h2_bits(__floats2half2_rn(v1.x, v1.y));
    o.w = h2_bits(__floats2half2_rn(v1.z, v1.w));
    dst[base] = o;
}

// ---------------- kernel 2: mma.sync fp16 GEMM ------------------------------
// D[m][n] = sum_k A[m][k] * W[n][k]   (M=16384, N=1536, K=512 fp16)
// CTA 128x128, K-chunk 32, 5-stage pipeline (issue hoisted above wait),
// 8 warps (4m x 2n), warp tile 32x64 = 2x8 m16n8k16 fragments.
// Mainloop FULLY UNROLLED: stage indices are compile-time constants.
__global__ void __launch_bounds__(256, 2) gemm_kernel() {
    extern __shared__ char smem[];
    const uint32_t sb = smem_u32(smem);
    const int tid  = threadIdx.x;
    const int lane = tid & 31;
    const int wid  = tid >> 5;
    const int m0 = blockIdx.y * TILE_M;
    const int n0 = blockIdx.x * TILE_N;
    const int g  = blockIdx.z;

    const __half* __restrict__ Ap = g ? g_Ah : g_Ax;
    const __half* __restrict__ Wp = g ? g_Wh : g_Wi;
    __half* __restrict__ Op = g ? g_HT : g_XT;

    // --- cp.async mapping: 512 16B chunks per matrix, 2 per thread ---
    const char* asrc[2];
    const char* bsrc[2];
    uint32_t    adst[2], bdst[2];
#pragma unroll
    for (int j = 0; j < 2; j++) {
        int q   = tid * 2 + j;
        int row = q >> 2;
        int cb  = (q & 3) * 16;            // byte offset within 64B row
        asrc[j] = (const char*)(Ap + (size_t)(m0 + row) * KS) + cb;
        bsrc[j] = (const char*)(Wp + (size_t)(n0 + row) * KS) + cb;
        adst[j] = (uint32_t)(row * ROW_STRIDE + cb);
        bdst[j] = (uint32_t)(A_STAGE_BYTES + row * ROW_STRIDE + cb);
    }

    // --- ldmatrix per-lane offsets ---
    const int wm = wid & 3;                // warp m index (0..3) -> 32 rows
    const int wn = wid >> 2;               // warp n index (0..1) -> 64 cols
    const int grp = lane >> 3;
    const int r8  = lane & 7;
    uint32_t aoff[2], boff[4];
#pragma unroll
    for (int t = 0; t < 2; t++)
        aoff[t] = (uint32_t)((wm * 32 + t * 16 + (grp & 1) * 8 + r8) * ROW_STRIDE
                             + (grp >> 1) * 16);
#pragma unroll
    for (int p = 0; p < 4; p++)
        boff[p] = (uint32_t)(A_STAGE_BYTES
                             + (wn * 64 + p * 16 + (grp >> 1) * 8 + r8) * ROW_STRIDE
                             + (grp & 1) * 16);

    float acc[2][8][4];
#pragma unroll
    for (int t = 0; t < 2; t++)
#pragma unroll
        for (int n = 0; n < 8; n++)
#pragma unroll
            for (int e = 0; e < 4; e++) acc[t][n][e] = 0.f;

    // --- pipeline ---
#define ISSUE_STAGE(c, stg)                                                  \
    do {                                                                     \
        if ((c) < NCHUNK) {                                                  \
            uint32_t s_ = sb + (uint32_t)(stg) * STAGE_BYTES;                \
            _Pragma("unroll")                                                \
            for (int j_ = 0; j_ < 2; j_++) {                                 \
                cp16(s_ + adst[j_], asrc[j_] + (size_t)(c) * 64);            \
                cp16(s_ + bdst[j_], bsrc[j_] + (size_t)(c) * 64);            \
            }                                                                \
        }                                                                    \
        asm volatile("cp.async.commit_group;" ::: "memory");                 \
    } while (0)

    ISSUE_STAGE(0, 0);
    ISSUE_STAGE(1, 1);
    ISSUE_STAGE(2, 2);

#pragma unroll
    for (int c = 0; c < NCHUNK; ++c) {
        const int wr = (c + 3) % STAGES;   // compile-time constant per instance
        const int rd = c % STAGES;
        // Issue ahead-of-wait: buffer 'wr' was last read at iteration c-2 and
        // a barrier at c-1 separates those reads from this write.
        ISSUE_STAGE(c + 3, wr);
        asm volatile("cp.async.wait_group 3;" ::: "memory");
        __syncthreads();

        const uint32_t s_ = sb + (uint32_t)rd * STAGE_BYTES;
#pragma unroll
        for (int ks = 0; ks < 2; ks++) {
            uint32_t Afr[2][4];
            uint32_t Bfr[8][2];
#pragma unroll
            for (int t = 0; t < 2; t++)
                ldm4(Afr[t], s_ + aoff[t] + ks * 32);
#pragma unroll
            for (int p = 0; p < 4; p++) {
                uint32_t v[4];
                ldm4(v, s_ + boff[p] + ks * 32);
                Bfr[2 * p][0]     = v[0];
                Bfr[2 * p][1]     = v[1];
                Bfr[2 * p + 1][0] = v[2];
                Bfr[2 * p + 1][1] = v[3];
            }
#pragma unroll
            for (int t = 0; t < 2; t++)
#pragma unroll
                for (int n = 0; n < 8; n++)
                    mma16816(acc[t][n], Afr[t], Bfr[n]);
        }
    }

    // --- epilogue: convert to fp16, STG.32 per fragment pair ---
    const int row_base = m0 + wm * 32 + (lane >> 2);
    const int col_base = n0 + wn * 64 + (lane & 3) * 2;
#pragma unroll
    for (int t = 0; t < 2; t++) {
#pragma unroll
        for (int n = 0; n < 8; n++) {
            int rr = row_base + t * 16;
            int cc = col_base + n * 8;
            __half2 v0 = __floats2half2_rn(acc[t][n][0], acc[t][n][1]);
            __half2 v1 = __floats2half2_rn(acc[t][n][2], acc[t][n][3]);
            *reinterpret_cast<__half2*>(Op + (size_t)rr * NH + cc)       = v0;
            *reinterpret_cast<__half2*>(Op + (size_t)(rr + 8) * NH + cc) = v1;
        }
    }
}

// ---------------- kernel 3: fused LN-GRU epilogue (vectorized) --------------
// one 256-thread block per batch row; thread t owns output columns 2t, 2t+1.
__global__ void __launch_bounds__(256) epilogue_kernel(
    const float* __restrict__ hx,
    const float* __restrict__ b_i,
    const float* __restrict__ b_h,
    float* __restrict__ out)
{
    const int r = blockIdx.x;
    const int t = threadIdx.x;
    const __half2* xrow = reinterpret_cast<const __half2*>(g_XT + (size_t)r * NH);
    const __half2* hrow = reinterpret_cast<const __half2*>(g_HT + (size_t)r * NH);

    float2 xv[3], hv[3];
    float sAx = 0.f, qAx = 0.f, sAh = 0.f, qAh = 0.f;
    float sBx = 0.f, qBx = 0.f, sBh = 0.f, qBh = 0.f;
#pragma unroll
    for (int i = 0; i < 3; i++) {
        int idx = t + 256 * i;                  // half2 index; col = 2*idx
        float2 xf = __half22float2(xrow[idx]);
        float2 hf = __half22float2(hrow[idx]);
        float2 bi2 = *reinterpret_cast<const float2*>(b_i + 2 * idx);
        float2 bh2 = *reinterpret_cast<const float2*>(b_h + 2 * idx);
        xf.x += bi2.x; xf.y += bi2.y;
        hf.x += bh2.x; hf.y += bh2.y;
        xv[i] = xf; hv[i] = hf;
        if (i < 2) {
            sAx += xf.x + xf.y; qAx += xf.x * xf.x + xf.y * xf.y;
            sAh += hf.x + hf.y; qAh += hf.x * hf.x + hf.y * hf.y;
        } else {
            sBx += xf.x + xf.y; qBx += xf.x * xf.x + xf.y * xf.y;
            sBh += hf.x + hf.y; qBh += hf.x * hf.x + hf.y * hf.y;
        }
    }

    // block-wide reduction of 8 partials
    float v[8] = {sAx, qAx, sAh, qAh, sBx, qBx, sBh, qBh};
#pragma unroll
    for (int k = 0; k < 8; k++)
#pragma unroll
        for (int off = 16; off; off >>= 1)
            v[k] += __shfl_xor_sync(0xffffffffu, v[k], off);

    __shared__ float red[8][8];
    __shared__ float stats[8];
    int lane = t & 31, w = t >> 5;
    if (lane == 0) {
#pragma unroll
        for (int k = 0; k < 8; k++) red[w][k] = v[k];
    }
    __syncthreads();
    if (t < 8) {
        float s = 0.f;
#pragma unroll
        for (int k = 0; k < 8; k++) s += red[k][t];
        stats[t] = s;
    }
    __syncthreads();

    const float invA = 1.f / 1024.f, invB = 1.f / 512.f;
    float mAx = stats[0] * invA, vAx = stats[1] * invA - mAx * mAx;
    float mAh = stats[2] * invA, vAh = stats[3] * invA - mAh * mAh;
    float mBx = stats[4] * invB, vBx = stats[5] * invB - mBx * mBx;
    float mBh = stats[6] * invB, vBh = stats[7] * invB - mBh * mBh;
    float rAx = rsqrtf(vAx + 1e-5f);
    float rAh = rsqrtf(vAh + 1e-5f);
    float rBx = rsqrtf(vBx + 1e-5f);
    float rBh = rsqrtf(vBh + 1e-5f);

    float gr0 = (xv[0].x - mAx) * rAx + (hv[0].x - mAh) * rAh;
    float gr1 = (xv[0].y - mAx) * rAx + (hv[0].y - mAh) * rAh;
    float gz0 = (xv[1].x - mAx) * rAx + (hv[1].x - mAh) * rAh;
    float gz1 = (xv[1].y - mAx) * rAx + (hv[1].y - mAh) * rAh;
    float rg0 = 1.f / (1.f + expf(-gr0));
    float rg1 = 1.f / (1.f + expf(-gr1));
    float zg0 = 1.f / (1.f + expf(-gz0));
    float zg1 = 1.f / (1.f + expf(-gz1));

    float n0v = tanhf((xv[2].x - mBx) * rBx + rg0 * ((hv[2].x - mBh) * rBh));
    float n1v = tanhf((xv[2].y - mBx) * rBx + rg1 * ((hv[2].y - mBh) * rBh));

    float2 hx2 = *reinterpret_cast<const float2*>(hx + (size_t)r * HH + 2 * t);
    float2 o;
    o.x = zg0 * hx2.x + (1.f - zg0) * n0v;
    o.y = zg1 * hx2.y + (1.f - zg1) * n1v;
    *reinterpret_cast<float2*>(out + (size_t)r * HH + 2 * t) = o;
}

// ---------------- launcher ----------------
extern "C" void kernel_launch(void* const* d_in, const int* in_sizes, int n_in,
                              void* d_out, int out_size) {
    const float* x  = (const float*)d_in[0];
    const float* hx = (const float*)d_in[1];
    const float* Wi = (const float*)d_in[2];
    const float* bi = (const float*)d_in[3];
    const float* Wh = (const float*)d_in[4];
    const float* bh = (const float*)d_in[5];
    float* out = (float*)d_out;
    (void)in_sizes; (void)n_in; (void)out_size;

    int total = 2 * TOT8A + 2 * TOT8W;
    convert_all_kernel<<<(total + 255) / 256, 256>>>(x, hx, Wi, Wh);

    static bool attr_set = false;
    if (!attr_set) {
        cudaFuncSetAttribute(gemm_kernel,
                             cudaFuncAttributeMaxDynamicSharedMemorySize, SMEM_BYTES);
        attr_set = true;
    }
    gemm_kernel<<<dim3(NH / TILE_N, NB / TILE_M, 2), 256, SMEM_BYTES>>>();

    epilogue_kernel<<<NB, 256>>>(hx, bi, bh, out);
}